// round 16
// baseline (speedup 1.0000x reference)
#include <cuda_runtime.h>
#include <cuda_bf16.h>
#include <math.h>
#include <stdint.h>

#define BB 64
#define NN 128
#define LL 64
#define DD 768
#define NEGV (-9e9f)
#define NCH 12            // K chunks of 64
#define STGB 65536        // bytes per pipeline stage
#define NSTG 3
#define MAXT 16           // max tiles per warp (K <= 128, 8 warps)

// -------- device scratch (no cudaMalloc allowed) ---------------------------
__device__ __nv_bfloat16 g_tAh[BB * NN * DD];
__device__ __nv_bfloat16 g_tAl[BB * NN * DD];
__device__ __nv_bfloat16 g_tBh[BB * LL * DD];
__device__ __nv_bfloat16 g_tBl[BB * LL * DD];
__device__ float g_S[BB * BB];
__device__ float g_P[BB * LL * NN];
__device__ int g_cA[BB];
__device__ int g_cB[BB];
__device__ int g_mapA[BB][NN];
__device__ int g_mapB[BB][LL];

// -------- helpers ----------------------------------------------------------
__device__ __forceinline__ uint32_t smem_u32(const void* p) {
    uint32_t a;
    asm("{ .reg .u64 t; cvta.to.shared.u64 t, %1; cvt.u32.u64 %0, t; }" : "=r"(a) : "l"(p));
    return a;
}
__device__ __forceinline__ void cp16(uint32_t dst, const void* src) {
    unsigned long long g = (unsigned long long)__cvta_generic_to_global(src);
    asm volatile("cp.async.cg.shared.global [%0], [%1], 16;" :: "r"(dst), "l"(g));
}
#define CP_COMMIT() asm volatile("cp.async.commit_group;" ::: "memory")

#define LDSM_X4(r0, r1, r2, r3, a) \
    asm volatile("ldmatrix.sync.aligned.m8n8.x4.shared.b16 {%0,%1,%2,%3}, [%4];" \
                 : "=r"(r0), "=r"(r1), "=r"(r2), "=r"(r3) : "r"(a))
#define LDSM_X2(r0, r1, a) \
    asm volatile("ldmatrix.sync.aligned.m8n8.x2.shared.b16 {%0,%1}, [%2];" \
                 : "=r"(r0), "=r"(r1) : "r"(a))

#define MMA_BF16(d, a, b) \
    asm("mma.sync.aligned.m16n8k16.row.col.f32.bf16.bf16.f32 " \
        "{%0,%1,%2,%3},{%4,%5,%6,%7},{%8,%9},{%0,%1,%2,%3};" \
        : "+f"((d)[0]), "+f"((d)[1]), "+f"((d)[2]), "+f"((d)[3]) \
        : "r"((a)[0]), "r"((a)[1]), "r"((a)[2]), "r"((a)[3]), \
          "r"((b)[0]), "r"((b)[1]))

// FMA-pipe exp (no MUFU): exp(x), x<=0, poly exp2 deg-6
__device__ __forceinline__ float fexp(float x) {
    float t = fmaxf(x * 1.44269504089f, -126.f);
    int   ni = __float2int_rn(t);
    float f  = t - (float)ni;
    float p = 1.54653240e-4f;
    p = fmaf(p, f, 1.33335581e-3f);
    p = fmaf(p, f, 9.61812910e-3f);
    p = fmaf(p, f, 5.55041087e-2f);
    p = fmaf(p, f, 2.40226507e-1f);
    p = fmaf(p, f, 6.93147182e-1f);
    p = fmaf(p, f, 1.0f);
    return __int_as_float(__float_as_int(p) + (ni << 23));
}

// f32x2 helpers (i2s kernel)
__device__ __forceinline__ void ffma2(unsigned long long &c, unsigned long long a,
                                      unsigned long long b) {
    asm("fma.rn.f32x2 %0, %1, %2, %0;" : "+l"(c) : "l"(a), "l"(b));
}
__device__ __forceinline__ unsigned long long pack2(float x, float y) {
    unsigned long long r;
    asm("mov.b64 %0, {%1, %2};" : "=l"(r) : "f"(x), "f"(y));
    return r;
}
__device__ __forceinline__ float2 unpack2(unsigned long long v) {
    float2 f;
    asm("mov.b64 {%0, %1}, %2;" : "=f"(f.x), "=f"(f.y) : "l"(v));
    return f;
}

// ---------------------------------------------------------------------------
// Kernel 0: mask-compacting f32 -> bf16 hi/lo split into pre-swizzled chunks.
// ---------------------------------------------------------------------------
__global__ void conv2(const float* __restrict__ text, const float* __restrict__ img,
                      const int* __restrict__ tmask, const int* __restrict__ imask)
{
    __shared__ int fA[NN], fB[LL];
    __shared__ int pfxA[NN + 1], pfxB[LL + 1];
    const int b  = blockIdx.x;
    const int dp = blockIdx.y;       // 0..3
    const int t  = threadIdx.x;      // 256

    if (t < NN) fA[t] = (tmask[b * NN + t] != 0);
    if (t < LL) fB[t] = (imask[b * LL + t] != 0);
    __syncthreads();
    if (t == 0) {
        int s = 0;
        for (int n = 0; n < NN; n++) { pfxA[n] = s; s += fA[n]; }
        pfxA[NN] = s;
        s = 0;
        for (int l = 0; l < LL; l++) { pfxB[l] = s; s += fB[l]; }
        pfxB[LL] = s;
    }
    __syncthreads();
    const int cA = pfxA[NN], cB = pfxB[LL];
    const int cApad = (cA + 15) & ~15;
    const int cBpad = (cB + 7) & ~7;

    if (dp == 0) {
        if (t == 0) { g_cA[b] = cA; g_cB[b] = cB; }
        if (t < NN && fA[t]) g_mapA[b][pfxA[t]] = t;
        if (t < LL && fB[t]) g_mapB[b][pfxB[t]] = t;
    }

    const int d0 = dp * 192;
    for (int idx = t; idx < NN * 192; idx += 256) {
        int n = idx / 192, d = d0 + idx % 192;
        if (fA[n]) {
            float v = text[(size_t)b * NN * DD + n * DD + d];
            __nv_bfloat16 hi = __float2bfloat16(v);
            __nv_bfloat16 lo = __float2bfloat16(v - __bfloat162float(hi));
            int r = pfxA[n];
            int c = d >> 6, kin = d & 63;
            int off = ((b * NCH + c) * NN + r) * 64 + (kin ^ ((r & 7) << 3));
            g_tAh[off] = hi; g_tAl[off] = lo;
        }
    }
    for (int idx = t; idx < (cApad - cA) * 192; idx += 256) {
        int r = cA + idx / 192, d = d0 + idx % 192;
        int c = d >> 6, kin = d & 63;
        int off = ((b * NCH + c) * NN + r) * 64 + (kin ^ ((r & 7) << 3));
        g_tAh[off] = __float2bfloat16(0.f); g_tAl[off] = __float2bfloat16(0.f);
    }
    for (int idx = t; idx < LL * 192; idx += 256) {
        int l = idx / 192, d = d0 + idx % 192;
        if (fB[l]) {
            float v = img[(size_t)b * LL * DD + l * DD + d];
            __nv_bfloat16 hi = __float2bfloat16(v);
            __nv_bfloat16 lo = __float2bfloat16(v - __bfloat162float(hi));
            int r = pfxB[l];
            int c = d >> 6, kin = d & 63;
            int off = ((b * NCH + c) * LL + r) * 64 + (kin ^ ((r & 7) << 3));
            g_tBh[off] = hi; g_tBl[off] = lo;
        }
    }
    for (int idx = t; idx < (cBpad - cB) * 192; idx += 256) {
        int r = cB + idx / 192, d = d0 + idx % 192;
        int c = d >> 6, kin = d & 63;
        int off = ((b * NCH + c) * LL + r) * 64 + (kin ^ ((r & 7) << 3));
        g_tBh[off] = __float2bfloat16(0.f); g_tBl[off] = __float2bfloat16(0.f);
    }
}

// ---------------------------------------------------------------------------
// Stage one K-chunk (64 k) of COMPACTED data, bounds-guarded.
// ---------------------------------------------------------------------------
__device__ __forceinline__ void issue_chunk(uint32_t B0, int i, int jg, int c, int t,
                                            int limA, int cB0p, int cB1p)
{
    const __nv_bfloat16* Ah = g_tAh + (size_t)(i * NCH + c) * (NN * 64);
    const __nv_bfloat16* Al = g_tAl + (size_t)(i * NCH + c) * (NN * 64);
#pragma unroll
    for (int q = 0; q < 4; q++) {
        int idx = t + q * 256;
        if (idx < limA) {
            cp16(B0 + idx * 16, Ah + idx * 8);
            cp16(B0 + 16384 + idx * 16, Al + idx * 8);
        }
    }
#pragma unroll
    for (int q = 0; q < 4; q++) {
        int idx = t + q * 256;
        int row = idx >> 3;
        int jj = row >> 6;
        int srow = row & 63;
        bool ok = jj ? (srow < cB1p) : (srow < cB0p);
        if (ok) {
            size_t so = (size_t)((jg * 2 + jj) * NCH + c) * (LL * 64) + (size_t)(srow * 8 + (idx & 7)) * 8;
            cp16(B0 + 32768 + idx * 16, g_tBh + so);
            cp16(B0 + 49152 + idx * 16, g_tBl + so);
        }
    }
}

// ---------------------------------------------------------------------------
// Kernel A: compacted bf16 3x GEMM + fused softmax epilogue.
// FLAT ROW-MAJOR TILE DEALING: the TM x TT tile grid is flattened and dealt
// in contiguous row-major runs of ceil(K/8) per warp (remainder distributed
// in SMSP-round-robin rank order) -> per-SMSP tile load ~ ceil(K/4)+1 vs the
// outer-product dealing's ntq(ng)*TM. A fragments reload only on row change.
// ---------------------------------------------------------------------------
__global__ __launch_bounds__(256, 1)
void ground9(const int* __restrict__ tmask)
{
    extern __shared__ __align__(16) char dsm[];   // 196608: 3 x 64KB stages / att
    __shared__ int   tm_s[NN];
    __shared__ int   mapA_s[NN];
    __shared__ int   mapB_s[NN];
    __shared__ float row_s1[NN];
    __shared__ float col_s2[LL];

    const int i  = blockIdx.y;
    const int jg = blockIdx.x;
    const int t  = threadIdx.x;
    const int wid = t >> 5, lane = t & 31;
    const uint32_t sb = smem_u32(dsm);

    const int cA  = g_cA[i];
    const int cApad = (cA + 15) & ~15;
    const int cB0 = g_cB[jg * 2];
    const int cB1 = g_cB[jg * 2 + 1];
    const int cB0p = (cB0 + 7) & ~7;
    const int cB1p = (cB1 + 7) & ~7;
    const int diag_jj = (jg == (i >> 1)) ? (i & 1) : -1;

    if (t < NN) {
        tm_s[t]   = tmask[i * NN + t];
        mapA_s[t] = g_mapA[i][t];
        mapB_s[t] = g_mapB[jg * 2 + (t >> 6)][t & 63];
    }

    // g_P default fill (diag CTA only)
    if (diag_jj >= 0 && t < NN) {
        const int cbd = diag_jj ? cB1 : cB0;
        int tmv = tmask[i * NN + t];
        float dflt = (tmv && cbd > 0) ? 0.f : (1.f / 64.f);
        float* Pp = g_P + (size_t)i * LL * NN + t;
#pragma unroll 8
        for (int l = 0; l < LL; l++) Pp[l * NN] = dflt;
    }

    // ---- flat row-major tile dealing (warp-uniform) -----------------------
    const int TM = cApad >> 4;
    const int T0 = cB0p >> 3, T1 = cB1p >> 3, TT = T0 + T1;
    const int K  = TM * TT;                    // total tiles, <= 128
    const int rank = ((wid & 3) << 1) | (wid >> 2);   // SMSP round-robin order
    const int Q = K >> 3, R = K & 7;
    const int start = rank * Q + (rank < R ? rank : R);
    const int myN = Q + (rank < R ? 1 : 0);    // <= MAXT

    // tile metadata: meta[u] = (mrow << 8) | ncol  (unrolled-register array)
    int meta[MAXT];
#pragma unroll
    for (int u = 0; u < MAXT; u++) {
        int p = start + u;
        int valid = (u < myN);
        int pp = valid ? p : 0;
        int r = (TT > 0) ? (pp / TT) : 0;
        int c = pp - r * TT;
        int ncol = (c < T0) ? (c << 3) : (64 + ((c - T0) << 3));
        meta[u] = (r << 12) | ncol;            // mrow = (meta>>12)<<4
    }

    // lane constants
    const int lr = lane & 15, half = lane >> 4;
    const int xorA = (lr & 7) << 4;
    const int blB = lane & 7;
    const int kBo = ((lane >> 3) & 1) << 4;
    const int xorB2 = blB << 4;

    float acc[MAXT][4];
#pragma unroll
    for (int u = 0; u < MAXT; u++)
#pragma unroll
        for (int r = 0; r < 4; r++) acc[u][r] = 0.f;

    const int limA = cApad * 8;

    // prime 2 stages
    issue_chunk(sb + 0 * STGB, i, jg, 0, t, limA, cB0p, cB1p);
    CP_COMMIT();
    issue_chunk(sb + 1 * STGB, i, jg, 1, t, limA, cB0p, cB1p);
    CP_COMMIT();

    int stg = 0;
    for (int c = 0; c < NCH; c++) {
        if (c + 1 < NCH) {
            asm volatile("cp.async.wait_group 1;" ::: "memory");
        } else {
            asm volatile("cp.async.wait_group 0;" ::: "memory");
        }
        __syncthreads();

        if (c + 2 < NCH) {
            int nst = stg + 2; if (nst >= NSTG) nst -= NSTG;
            issue_chunk(sb + nst * STGB, i, jg, c + 2, t, limA, cB0p, cB1p);
            CP_COMMIT();
        }

        const uint32_t SB = sb + stg * STGB;
        const uint32_t Ah = SB, Al = SB + 16384, Bh = SB + 32768, Bl = SB + 49152;
#pragma unroll
        for (int s = 0; s < 4; s++) {
            const int kaA = ((s * 32) | (half << 4)) ^ xorA;
            const int kaB = ((s * 32) | kBo) ^ xorB2;

            uint32_t ah[4], al[4];
            int prow = -1;                      // row currently in A fragments
#pragma unroll
            for (int u = 0; u < MAXT; u++) {
                if (u < myN) {                  // warp-uniform
                    int mr = meta[u] >> 12;     // row tile index
                    if (mr != prow) {           // warp-uniform branch
                        int rowa = (mr << 4) + lr;
                        LDSM_X4(ah[0], ah[1], ah[2], ah[3], Ah + rowa * 128 + kaA);
                        LDSM_X4(al[0], al[1], al[2], al[3], Al + rowa * 128 + kaA);
                        prow = mr;
                    }
                    uint32_t off = (uint32_t)((meta[u] & 0xFFF) + blB) * 128 + kaB;
                    uint32_t bh[2], bl2[2];
                    LDSM_X2(bh[0],  bh[1],  Bh + off);
                    LDSM_X2(bl2[0], bl2[1], Bl + off);
                    MMA_BF16(acc[u], ah, bh);
                    MMA_BF16(acc[u], ah, bl2);
                    MMA_BF16(acc[u], al, bh);
                }
            }
        }
        if (++stg >= NSTG) stg = 0;
    }
    __syncthreads();   // mainloop done before att overwrites stages

    // ---- att tile -> SMEM (compacted coords), pitch 132 -------------------
    float* att = (float*)dsm;
    const int gr = lane >> 2, cp2 = (lane & 3) * 2;
#pragma unroll
    for (int u = 0; u < MAXT; u++) {
        if (u < myN) {
            int row = ((meta[u] >> 12) << 4) + gr;
            int col = (meta[u] & 0xFFF) + cp2;
            float* d = acc[u];
            float2 v0, v1;
            v0.x = (d[0] != 0.f) ? d[0] : NEGV;
            v0.y = (d[1] != 0.f) ? d[1] : NEGV;
            v1.x = (d[2] != 0.f) ? d[2] : NEGV;
            v1.y = (d[3] != 0.f) ? d[3] : NEGV;
            *(float2*)&att[row * 132 + col]       = v0;
            *(float2*)&att[(row + 8) * 132 + col] = v1;
        }
    }
    __syncthreads();

    // ---- epilogue per image batch -----------------------------------------
    for (int jj = 0; jj < 2; jj++) {
        const int j   = jg * 2 + jj;
        const int cbj = jj ? cB1 : cB0;

        {   // row softmax: 2 threads per row; unconditional store (val or 0)
            const int rr = t >> 1, sg = t & 1;
            const float* ar = att + rr * 132 + jj * 64;
            float mx = -INFINITY;
            for (int c2 = sg; c2 < cbj; c2 += 2) mx = fmaxf(mx, ar[c2]);
            mx = fmaxf(mx, __shfl_xor_sync(~0u, mx, 1));
            float Z = 0.f, num = 0.f;
            for (int c2 = sg; c2 < cbj; c2 += 2) {
                float av = ar[c2];
                float e = fexp(av - mx);
                Z += e;
                num += e * av;
            }
            Z += __shfl_xor_sync(~0u, Z, 1);
            num += __shfl_xor_sync(~0u, num, 1);
            float inv = __frcp_rn(Z);
            if (sg == 0) row_s1[rr] = (rr < cA && cbj > 0) ? num * inv : 0.f;
            if (jj == diag_jj && rr < cA && cbj > 0) {
                int n = mapA_s[rr];
                float* Pp = g_P + (size_t)i * LL * NN + n;
                for (int c2 = sg; c2 < cbj; c2 += 2)
                    Pp[mapB_s[jj * 64 + c2] * NN] = fexp(ar[c2] - mx) * inv;
            }
        }
        {   // col softmax
            const int cc = t >> 2, seg = t & 3;
            const int rN = cA;
            const float* ac = att + jj * 64 + cc;
            float mx = -INFINITY;
            for (int r = seg; r < rN; r += 4) mx = fmaxf(mx, ac[r * 132]);
            mx = fmaxf(mx, __shfl_xor_sync(~0u, mx, 1));
            mx = fmaxf(mx, __shfl_xor_sync(~0u, mx, 2));
            float Z = 0.f, num = 0.f;
            for (int r = seg; r < rN; r += 4) {
                float av = ac[r * 132];
                float e = fexp(av - mx);
                Z += e;
                num += e * av;
            }
            Z += __shfl_xor_sync(~0u, Z, 1);  Z += __shfl_xor_sync(~0u, Z, 2);
            num += __shfl_xor_sync(~0u, num, 1); num += __shfl_xor_sync(~0u, num, 2);
            if (seg == 0) col_s2[cc] = (cc < cbj && rN > 0) ? num * __frcp_rn(Z) : 0.f;
        }
        __syncthreads();

        if (t < 32) {
            float s = row_s1[t * 4] + row_s1[t * 4 + 1] + row_s1[t * 4 + 2] + row_s1[t * 4 + 3]
                    + col_s2[t * 2] + col_s2[t * 2 + 1];
#pragma unroll
            for (int o = 16; o > 0; o >>= 1) s += __shfl_xor_sync(~0u, s, o);
            if (t == 0) g_S[i * BB + j] = s * (1.f / 128.f);
        }
        __syncthreads();
    }
}

// ---------------------------------------------------------------------------
// Kernel B: contrastive loss from S
// ---------------------------------------------------------------------------
__global__ void loss_kernel(float* __restrict__ out)
{
    __shared__ float Ss[BB * BB];
    __shared__ float part[BB];
    const int t = threadIdx.x;  // 64
    for (int k = t; k < BB * BB; k += BB) Ss[k] = g_S[k];
    __syncthreads();
    float mx = -INFINITY;
    for (int c = 0; c < BB; c++) mx = fmaxf(mx, Ss[t * BB + c]);
    float Z = 0.f;
    for (int c = 0; c < BB; c++) Z += expf(Ss[t * BB + c] - mx);
    float lse_r = mx + logf(Z);
    float mc = -INFINITY;
    for (int r = 0; r < BB; r++) mc = fmaxf(mc, Ss[r * BB + t]);
    float Zc = 0.f;
    for (int r = 0; r < BB; r++) Zc += expf(Ss[r * BB + t] - mc);
    float lse_c = mc + logf(Zc);
    float d = Ss[t * BB + t];
    part[t] = (d - lse_r) + (d - lse_c);
    __syncthreads();
    if (t == 0) {
        float s = 0.f;
        for (int k = 0; k < BB; k++) s += part[k];
        out[0] = -s / (float)BB;
    }
}

// ---------------------------------------------------------------------------
// Kernel C: text_emb_i2s[b] = P[b] @ V[b]  (P stored [l][n])
// ---------------------------------------------------------------------------
__global__ __launch_bounds__(256)
void i2s_kernel(const float* __restrict__ img, float* __restrict__ out)
{
    extern __shared__ float cs[];
    float* V_s = cs;
    float* P_s = cs + 64 * 128;
    const int b = blockIdx.y, dc = blockIdx.x, t = threadIdx.x;
    const int dq = t & 31, ng = t >> 5;

    const float* Vg = img + (size_t)b * LL * DD + dc * 128;
#pragma unroll
    for (int q = 0; q < 8; q++) {
        int f = t + q * 256;
        int l = f >> 5, c4 = f & 31;
        *(float4*)&V_s[l * 128 + c4 * 4] = *(const float4*)(Vg + l * DD + c4 * 4);
    }
    const float* Pgp = g_P + (size_t)b * LL * NN;
#pragma unroll
    for (int q = 0; q < 8; q++) {
        int f = t + q * 256;
        *(float4*)&P_s[f * 4] = *(const float4*)(Pgp + f * 4);
    }
    __syncthreads();

    unsigned long long acc[8][4];
#pragma unroll
    for (int nn = 0; nn < 8; nn++)
#pragma unroll
        for (int dd = 0; dd < 4; dd++) acc[nn][dd] = 0ull;

#pragma unroll 4
    for (int l = 0; l < LL; l++) {
        float v0 = V_s[l * 128 + dq];
        float v1 = V_s[l * 128 + dq + 32];
        float v2 = V_s[l * 128 + dq + 64];
        float v3 = V_s[l * 128 + dq + 96];
        unsigned long long bv0 = pack2(v0, v0), bv1 = pack2(v1, v1);
        unsigned long long bv2 = pack2(v2, v2), bv3 = pack2(v3, v3);
#pragma unroll
        for (int nn = 0; nn < 8; nn++) {
            int np = ng * 8 + nn;
            unsigned long long a = *(const unsigned long long*)&P_s[l * 128 + np * 2];
            ffma2(acc[nn][0], a, bv0);
            ffma2(acc[nn][1], a, bv1);
            ffma2(acc[nn][2], a, bv2);
            ffma2(acc[nn][3], a, bv3);
        }
    }
    float* ob = out + 1 + (size_t)b * NN * DD + dc * 128;
#pragma unroll
    for (int nn = 0; nn < 8; nn++) {
        int n0 = (ng * 8 + nn) * 2;
#pragma unroll
        for (int dd = 0; dd < 4; dd++) {
            float2 v = unpack2(acc[nn][dd]);
            ob[(size_t)n0 * DD + dd * 32 + dq]       = v.x;
            ob[(size_t)(n0 + 1) * DD + dd * 32 + dq] = v.y;
        }
    }
}

// ---------------------------------------------------------------------------
extern "C" void kernel_launch(void* const* d_in, const int* in_sizes, int n_in,
                              void* d_out, int out_size)
{
    (void)in_sizes; (void)n_in; (void)out_size;
    const float* text = (const float*)d_in[0];
    const float* img  = (const float*)d_in[1];
    const int* tmask  = (const int*)d_in[2];
    const int* imask  = (const int*)d_in[3];
    float* out = (float*)d_out;

    cudaFuncSetAttribute(ground9, cudaFuncAttributeMaxDynamicSharedMemorySize, NSTG * STGB);
    cudaFuncSetAttribute(i2s_kernel, cudaFuncAttributeMaxDynamicSharedMemorySize, 65536);

    conv2<<<dim3(BB, 4), 256>>>(text, img, tmask, imask);
    ground9<<<dim3(32, BB), 256, NSTG * STGB>>>(tmask);
    loss_kernel<<<1, 64>>>(out);
    i2s_kernel<<<dim3(6, BB), 256, 65536>>>(img, out);
}

// round 17
// speedup vs baseline: 1.0320x; 1.0320x over previous
#include <cuda_runtime.h>
#include <cuda_bf16.h>
#include <math.h>
#include <stdint.h>

#define BB 64
#define NN 128
#define LL 64
#define DD 768
#define NEGV (-9e9f)
#define NCH 12            // K chunks of 64
#define STGB 65536        // bytes per pipeline stage
#define NSTG 3

// -------- device scratch (no cudaMalloc allowed) ---------------------------
__device__ __nv_bfloat16 g_tAh[BB * NN * DD];
__device__ __nv_bfloat16 g_tAl[BB * NN * DD];
__device__ __nv_bfloat16 g_tBh[BB * LL * DD];
__device__ __nv_bfloat16 g_tBl[BB * LL * DD];
__device__ float g_S[BB * BB];
__device__ float g_P[BB * LL * NN];
__device__ int g_cA[BB];
__device__ int g_cB[BB];
__device__ int g_mapA[BB][NN];
__device__ int g_mapB[BB][LL];

// -------- helpers ----------------------------------------------------------
__device__ __forceinline__ uint32_t smem_u32(const void* p) {
    uint32_t a;
    asm("{ .reg .u64 t; cvta.to.shared.u64 t, %1; cvt.u32.u64 %0, t; }" : "=r"(a) : "l"(p));
    return a;
}
__device__ __forceinline__ void cp16(uint32_t dst, const void* src) {
    unsigned long long g = (unsigned long long)__cvta_generic_to_global(src);
    asm volatile("cp.async.cg.shared.global [%0], [%1], 16;" :: "r"(dst), "l"(g));
}
#define CP_COMMIT() asm volatile("cp.async.commit_group;" ::: "memory")

#define LDSM_X4(r0, r1, r2, r3, a) \
    asm volatile("ldmatrix.sync.aligned.m8n8.x4.shared.b16 {%0,%1,%2,%3}, [%4];" \
                 : "=r"(r0), "=r"(r1), "=r"(r2), "=r"(r3) : "r"(a))
#define LDSM_X2(r0, r1, a) \
    asm volatile("ldmatrix.sync.aligned.m8n8.x2.shared.b16 {%0,%1}, [%2];" \
                 : "=r"(r0), "=r"(r1) : "r"(a))

#define MMA_BF16(d, a, b) \
    asm("mma.sync.aligned.m16n8k16.row.col.f32.bf16.bf16.f32 " \
        "{%0,%1,%2,%3},{%4,%5,%6,%7},{%8,%9},{%0,%1,%2,%3};" \
        : "+f"((d)[0]), "+f"((d)[1]), "+f"((d)[2]), "+f"((d)[3]) \
        : "r"((a)[0]), "r"((a)[1]), "r"((a)[2]), "r"((a)[3]), \
          "r"((b)[0]), "r"((b)[1]))

// FMA-pipe exp (no MUFU): exp(x), x<=0, poly exp2 deg-6
__device__ __forceinline__ float fexp(float x) {
    float t = fmaxf(x * 1.44269504089f, -126.f);
    int   ni = __float2int_rn(t);
    float f  = t - (float)ni;
    float p = 1.54653240e-4f;
    p = fmaf(p, f, 1.33335581e-3f);
    p = fmaf(p, f, 9.61812910e-3f);
    p = fmaf(p, f, 5.55041087e-2f);
    p = fmaf(p, f, 2.40226507e-1f);
    p = fmaf(p, f, 6.93147182e-1f);
    p = fmaf(p, f, 1.0f);
    return __int_as_float(__float_as_int(p) + (ni << 23));
}

// f32x2 helpers (i2s kernel)
__device__ __forceinline__ void ffma2(unsigned long long &c, unsigned long long a,
                                      unsigned long long b) {
    asm("fma.rn.f32x2 %0, %1, %2, %0;" : "+l"(c) : "l"(a), "l"(b));
}
__device__ __forceinline__ unsigned long long pack2(float x, float y) {
    unsigned long long r;
    asm("mov.b64 %0, {%1, %2};" : "=l"(r) : "f"(x), "f"(y));
    return r;
}
__device__ __forceinline__ float2 unpack2(unsigned long long v) {
    float2 f;
    asm("mov.b64 {%0, %1}, %2;" : "=f"(f.x), "=f"(f.y) : "l"(v));
    return f;
}

// ---------------------------------------------------------------------------
// Kernel 0: mask-compacting f32 -> bf16 hi/lo split into pre-swizzled chunks.
// ---------------------------------------------------------------------------
__global__ void conv2(const float* __restrict__ text, const float* __restrict__ img,
                      const int* __restrict__ tmask, const int* __restrict__ imask)
{
    __shared__ int fA[NN], fB[LL];
    __shared__ int pfxA[NN + 1], pfxB[LL + 1];
    const int b  = blockIdx.x;
    const int dp = blockIdx.y;       // 0..3
    const int t  = threadIdx.x;      // 256

    if (t < NN) fA[t] = (tmask[b * NN + t] != 0);
    if (t < LL) fB[t] = (imask[b * LL + t] != 0);
    __syncthreads();
    if (t == 0) {
        int s = 0;
        for (int n = 0; n < NN; n++) { pfxA[n] = s; s += fA[n]; }
        pfxA[NN] = s;
        s = 0;
        for (int l = 0; l < LL; l++) { pfxB[l] = s; s += fB[l]; }
        pfxB[LL] = s;
    }
    __syncthreads();
    const int cA = pfxA[NN], cB = pfxB[LL];
    const int cApad = (cA + 15) & ~15;
    const int cBpad = (cB + 7) & ~7;

    if (dp == 0) {
        if (t == 0) { g_cA[b] = cA; g_cB[b] = cB; }
        if (t < NN && fA[t]) g_mapA[b][pfxA[t]] = t;
        if (t < LL && fB[t]) g_mapB[b][pfxB[t]] = t;
    }

    const int d0 = dp * 192;
    for (int idx = t; idx < NN * 192; idx += 256) {
        int n = idx / 192, d = d0 + idx % 192;
        if (fA[n]) {
            float v = text[(size_t)b * NN * DD + n * DD + d];
            __nv_bfloat16 hi = __float2bfloat16(v);
            __nv_bfloat16 lo = __float2bfloat16(v - __bfloat162float(hi));
            int r = pfxA[n];
            int c = d >> 6, kin = d & 63;
            int off = ((b * NCH + c) * NN + r) * 64 + (kin ^ ((r & 7) << 3));
            g_tAh[off] = hi; g_tAl[off] = lo;
        }
    }
    for (int idx = t; idx < (cApad - cA) * 192; idx += 256) {
        int r = cA + idx / 192, d = d0 + idx % 192;
        int c = d >> 6, kin = d & 63;
        int off = ((b * NCH + c) * NN + r) * 64 + (kin ^ ((r & 7) << 3));
        g_tAh[off] = __float2bfloat16(0.f); g_tAl[off] = __float2bfloat16(0.f);
    }
    for (int idx = t; idx < LL * 192; idx += 256) {
        int l = idx / 192, d = d0 + idx % 192;
        if (fB[l]) {
            float v = img[(size_t)b * LL * DD + l * DD + d];
            __nv_bfloat16 hi = __float2bfloat16(v);
            __nv_bfloat16 lo = __float2bfloat16(v - __bfloat162float(hi));
            int r = pfxB[l];
            int c = d >> 6, kin = d & 63;
            int off = ((b * NCH + c) * LL + r) * 64 + (kin ^ ((r & 7) << 3));
            g_tBh[off] = hi; g_tBl[off] = lo;
        }
    }
    for (int idx = t; idx < (cBpad - cB) * 192; idx += 256) {
        int r = cB + idx / 192, d = d0 + idx % 192;
        int c = d >> 6, kin = d & 63;
        int off = ((b * NCH + c) * LL + r) * 64 + (kin ^ ((r & 7) << 3));
        g_tBh[off] = __float2bfloat16(0.f); g_tBl[off] = __float2bfloat16(0.f);
    }
}

// ---------------------------------------------------------------------------
// Stage one K-chunk (64 k) of COMPACTED data, bounds-guarded.
// ---------------------------------------------------------------------------
__device__ __forceinline__ void issue_chunk(uint32_t B0, int i, int jg, int c, int t,
                                            int limA, int cB0p, int cB1p)
{
    const __nv_bfloat16* Ah = g_tAh + (size_t)(i * NCH + c) * (NN * 64);
    const __nv_bfloat16* Al = g_tAl + (size_t)(i * NCH + c) * (NN * 64);
#pragma unroll
    for (int q = 0; q < 4; q++) {
        int idx = t + q * 256;
        if (idx < limA) {
            cp16(B0 + idx * 16, Ah + idx * 8);
            cp16(B0 + 16384 + idx * 16, Al + idx * 8);
        }
    }
#pragma unroll
    for (int q = 0; q < 4; q++) {
        int idx = t + q * 256;
        int row = idx >> 3;
        int jj = row >> 6;
        int srow = row & 63;
        bool ok = jj ? (srow < cB1p) : (srow < cB0p);
        if (ok) {
            size_t so = (size_t)((jg * 2 + jj) * NCH + c) * (LL * 64) + (size_t)(srow * 8 + (idx & 7)) * 8;
            cp16(B0 + 32768 + idx * 16, g_tBh + so);
            cp16(B0 + 49152 + idx * 16, g_tBl + so);
        }
    }
}

// ---------------------------------------------------------------------------
// Kernel A: compacted bf16 3x GEMM + fused softmax epilogue.
// R15 structure (3-stage pipeline, outer-product tiles with full reuse) +
// LPT SLOT PAIRING: the 8 (mh, ng) slots are greedily packed onto the 4
// SMSPs by descending load so the per-SMSP MMA totals are near-balanced.
// ---------------------------------------------------------------------------
__global__ __launch_bounds__(256, 1)
void ground10(const int* __restrict__ tmask)
{
    extern __shared__ __align__(16) char dsm[];   // 196608: 3 x 64KB stages / att
    __shared__ int   tm_s[NN];
    __shared__ int   mapA_s[NN];
    __shared__ int   mapB_s[NN];
    __shared__ float row_s1[NN];
    __shared__ float col_s2[LL];

    const int i  = blockIdx.y;
    const int jg = blockIdx.x;
    const int t  = threadIdx.x;
    const int wid = t >> 5, lane = t & 31;
    const uint32_t sb = smem_u32(dsm);

    const int cA  = g_cA[i];
    const int cApad = (cA + 15) & ~15;
    const int cB0 = g_cB[jg * 2];
    const int cB1 = g_cB[jg * 2 + 1];
    const int cB0p = (cB0 + 7) & ~7;
    const int cB1p = (cB1 + 7) & ~7;
    const int diag_jj = (jg == (i >> 1)) ? (i & 1) : -1;

    if (t < NN) {
        tm_s[t]   = tmask[i * NN + t];
        mapA_s[t] = g_mapA[i][t];
        mapB_s[t] = g_mapB[jg * 2 + (t >> 6)][t & 63];
    }

    // g_P default fill (diag CTA only)
    if (diag_jj >= 0 && t < NN) {
        const int cbd = diag_jj ? cB1 : cB0;
        int tmv = tmask[i * NN + t];
        float dflt = (tmv && cbd > 0) ? 0.f : (1.f / 64.f);
        float* Pp = g_P + (size_t)i * LL * NN + t;
#pragma unroll 8
        for (int l = 0; l < LL; l++) Pp[l * NN] = dflt;
    }

    // ---- LPT slot-to-SMSP assignment (warp-uniform, identical all warps) --
    const int TM = cApad >> 4;
    const int T0 = cB0p >> 3, T1 = cB1p >> 3, TT = T0 + T1;
    int tmAe0 = (TM + 1) >> 1, tmAe1 = TM >> 1;
    int ntqv[4];
#pragma unroll
    for (int g2 = 0; g2 < 4; g2++) ntqv[g2] = (TT > g2) ? ((TT - g2 + 3) >> 2) : 0;

    int myslot = 0;
    {
        int sload[4] = {0, 0, 0, 0}, scnt[4] = {0, 0, 0, 0};
        unsigned used = 0;
#pragma unroll 1
        for (int it = 0; it < 8; it++) {
            int bs = 0, bl = -1;
#pragma unroll
            for (int sl = 0; sl < 8; sl++)
                if (!((used >> sl) & 1u)) {
                    int L = ((sl >> 2) ? tmAe1 : tmAe0) * ntqv[sl & 3];
                    if (L > bl) { bl = L; bs = sl; }
                }
            used |= 1u << bs;
            int ts = -1;
#pragma unroll
            for (int s2 = 0; s2 < 4; s2++)
                if (scnt[s2] < 2 && (ts < 0 || sload[s2] < sload[ts])) ts = s2;
            if (ts == (wid & 3) && scnt[ts] == (wid >> 2)) myslot = bs;
            sload[ts] += bl;
            scnt[ts]++;
        }
    }
    const int mh = myslot >> 2;
    const int ng = myslot & 3;

    int mrow[4]; int tmA = 0;
#pragma unroll
    for (int mf = 0; mf < 4; mf++) {
        int r = mh + 2 * mf;
        if (r < TM) mrow[tmA++] = r << 4;
    }
    int ncol[4]; int ntq = 0;
#pragma unroll
    for (int q = 0; q < 4; q++) {
        int p = ng + 4 * q;
        if (p < TT) ncol[ntq++] = (p < T0) ? (p << 3) : (64 + ((p - T0) << 3));
    }

    // lane constants
    const int lr = lane & 15, half = lane >> 4;
    const int xorA = (lr & 7) << 4;
    const int blB = lane & 7;
    const int kBo = ((lane >> 3) & 1) << 4;
    const int xorB2 = blB << 4;

    float acc[4][4][4];
#pragma unroll
    for (int a = 0; a < 4; a++)
#pragma unroll
        for (int b = 0; b < 4; b++)
#pragma unroll
            for (int r = 0; r < 4; r++) acc[a][b][r] = 0.f;

    const int limA = cApad * 8;

    // prime 2 stages
    issue_chunk(sb + 0 * STGB, i, jg, 0, t, limA, cB0p, cB1p);
    CP_COMMIT();
    issue_chunk(sb + 1 * STGB, i, jg, 1, t, limA, cB0p, cB1p);
    CP_COMMIT();

    int stg = 0;
    for (int c = 0; c < NCH; c++) {
        if (c + 1 < NCH) {
            asm volatile("cp.async.wait_group 1;" ::: "memory");
        } else {
            asm volatile("cp.async.wait_group 0;" ::: "memory");
        }
        __syncthreads();

        if (c + 2 < NCH) {
            int nst = stg + 2; if (nst >= NSTG) nst -= NSTG;
            issue_chunk(sb + nst * STGB, i, jg, c + 2, t, limA, cB0p, cB1p);
            CP_COMMIT();
        }

        const uint32_t SB = sb + stg * STGB;
        const uint32_t Ah = SB, Al = SB + 16384, Bh = SB + 32768, Bl = SB + 49152;
#pragma unroll
        for (int s = 0; s < 4; s++) {
            const int kb = s * 32;
            const int kaA = (kb | (half << 4)) ^ xorA;
            const int kaB = (kb | kBo) ^ xorB2;

            uint32_t ah[4][4], al[4][4], bh[4][2], bl2[4][2];
#pragma unroll
            for (int v = 0; v < 4; v++) if (v < tmA) {
                int row = mrow[v] + lr;
                LDSM_X4(ah[v][0], ah[v][1], ah[v][2], ah[v][3], Ah + row * 128 + kaA);
                LDSM_X4(al[v][0], al[v][1], al[v][2], al[v][3], Al + row * 128 + kaA);
            }
#pragma unroll
            for (int q = 0; q < 4; q++) if (q < ntq) {
                uint32_t off = (uint32_t)(ncol[q] + blB) * 128 + kaB;
                LDSM_X2(bh[q][0],  bh[q][1],  Bh + off);
                LDSM_X2(bl2[q][0], bl2[q][1], Bl + off);
            }
#pragma unroll
            for (int v = 0; v < 4; v++) if (v < tmA)
#pragma unroll
                for (int q = 0; q < 4; q++) if (q < ntq)
                    MMA_BF16(acc[v][q], ah[v], bh[q]);
#pragma unroll
            for (int v = 0; v < 4; v++) if (v < tmA)
#pragma unroll
                for (int q = 0; q < 4; q++) if (q < ntq)
                    MMA_BF16(acc[v][q], ah[v], bl2[q]);
#pragma unroll
            for (int v = 0; v < 4; v++) if (v < tmA)
#pragma unroll
                for (int q = 0; q < 4; q++) if (q < ntq)
                    MMA_BF16(acc[v][q], al[v], bh[q]);
        }
        if (++stg >= NSTG) stg = 0;
    }
    __syncthreads();   // mainloop done before att overwrites stages

    // ---- att tile -> SMEM (compacted coords), pitch 132 -------------------
    float* att = (float*)dsm;
    const int gr = lane >> 2, cp2 = (lane & 3) * 2;
#pragma unroll
    for (int v = 0; v < 4; v++) if (v < tmA)
#pragma unroll
        for (int q = 0; q < 4; q++) if (q < ntq) {
            int row = mrow[v] + gr;
            int col = ncol[q] + cp2;
            float* d = acc[v][q];
            float2 v0, v1;
            v0.x = (d[0] != 0.f) ? d[0] : NEGV;
            v0.y = (d[1] != 0.f) ? d[1] : NEGV;
            v1.x = (d[2] != 0.f) ? d[2] : NEGV;
            v1.y = (d[3] != 0.f) ? d[3] : NEGV;
            *(float2*)&att[row * 132 + col]       = v0;
            *(float2*)&att[(row + 8) * 132 + col] = v1;
        }
    __syncthreads();

    // ---- epilogue per image batch -----------------------------------------
    for (int jj = 0; jj < 2; jj++) {
        const int j   = jg * 2 + jj;
        const int cbj = jj ? cB1 : cB0;

        {   // row softmax: 2 threads per row; unconditional store (val or 0)
            const int rr = t >> 1, sg = t & 1;
            const float* ar = att + rr * 132 + jj * 64;
            float mx = -INFINITY;
            for (int c2 = sg; c2 < cbj; c2 += 2) mx = fmaxf(mx, ar[c2]);
            mx = fmaxf(mx, __shfl_xor_sync(~0u, mx, 1));
            float Z = 0.f, num = 0.f;
            for (int c2 = sg; c2 < cbj; c2 += 2) {
                float av = ar[c2];
                float e = fexp(av - mx);
                Z += e;
                num += e * av;
            }
            Z += __shfl_xor_sync(~0u, Z, 1);
            num += __shfl_xor_sync(~0u, num, 1);
            float inv = __frcp_rn(Z);
            if (sg == 0) row_s1[rr] = (rr < cA && cbj > 0) ? num * inv : 0.f;
            if (jj == diag_jj && rr < cA && cbj > 0) {
                int n = mapA_s[rr];
                float* Pp = g_P + (size_t)i * LL * NN + n;
                for (int c2 = sg; c2 < cbj; c2 += 2)
                    Pp[mapB_s[jj * 64 + c2] * NN] = fexp(ar[c2] - mx) * inv;
            }
        }
        {   // col softmax
            const int cc = t >> 2, seg = t & 3;
            const int rN = cA;
            const float* ac = att + jj * 64 + cc;
            float mx = -INFINITY;
            for (int r = seg; r < rN; r += 4) mx = fmaxf(mx, ac[r * 132]);
            mx = fmaxf(mx, __shfl_xor_sync(~0u, mx, 1));
            mx = fmaxf(mx, __shfl_xor_sync(~0u, mx, 2));
            float Z = 0.f, num = 0.f;
            for (int r = seg; r < rN; r += 4) {
                float av = ac[r * 132];
                float e = fexp(av - mx);
                Z += e;
                num += e * av;
            }
            Z += __shfl_xor_sync(~0u, Z, 1);  Z += __shfl_xor_sync(~0u, Z, 2);
            num += __shfl_xor_sync(~0u, num, 1); num += __shfl_xor_sync(~0u, num, 2);
            if (seg == 0) col_s2[cc] = (cc < cbj && rN > 0) ? num * __frcp_rn(Z) : 0.f;
        }
        __syncthreads();

        if (t < 32) {
            float s = row_s1[t * 4] + row_s1[t * 4 + 1] + row_s1[t * 4 + 2] + row_s1[t * 4 + 3]
                    + col_s2[t * 2] + col_s2[t * 2 + 1];
#pragma unroll
            for (int o = 16; o > 0; o >>= 1) s += __shfl_xor_sync(~0u, s, o);
            if (t == 0) g_S[i * BB + j] = s * (1.f / 128.f);
        }
        __syncthreads();
    }
}

// ---------------------------------------------------------------------------
// Kernel B: contrastive loss from S
// ---------------------------------------------------------------------------
__global__ void loss_kernel(float* __restrict__ out)
{
    __shared__ float Ss[BB * BB];
    __shared__ float part[BB];
    const int t = threadIdx.x;  // 64
    for (int k = t; k < BB * BB; k += BB) Ss[k] = g_S[k];
    __syncthreads();
    float mx = -INFINITY;
    for (int c = 0; c < BB; c++) mx = fmaxf(mx, Ss[t * BB + c]);
    float Z = 0.f;
    for (int c = 0; c < BB; c++) Z += expf(Ss[t * BB + c] - mx);
    float lse_r = mx + logf(Z);
    float mc = -INFINITY;
    for (int r = 0; r < BB; r++) mc = fmaxf(mc, Ss[r * BB + t]);
    float Zc = 0.f;
    for (int r = 0; r < BB; r++) Zc += expf(Ss[r * BB + t] - mc);
    float lse_c = mc + logf(Zc);
    float d = Ss[t * BB + t];
    part[t] = (d - lse_r) + (d - lse_c);
    __syncthreads();
    if (t == 0) {
        float s = 0.f;
        for (int k = 0; k < BB; k++) s += part[k];
        out[0] = -s / (float)BB;
    }
}

// ---------------------------------------------------------------------------
// Kernel C: text_emb_i2s[b] = P[b] @ V[b]  (P stored [l][n])
// 64-col d-chunks, grid (12, 64), 48KB smem -> 4 CTAs/SM.
// ---------------------------------------------------------------------------
__global__ __launch_bounds__(256)
void i2s_kernel(const float* __restrict__ img, float* __restrict__ out)
{
    extern __shared__ float cs[];
    float* V_s = cs;              // [64][64] d-chunk of V (16KB)
    float* P_s = cs + 64 * 64;    // [64][128] = [l][n]    (32KB)
    const int b = blockIdx.y, dc = blockIdx.x, t = threadIdx.x;
    const int dq = t & 31, ng = t >> 5;

    const float* Vg = img + (size_t)b * LL * DD + dc * 64;
#pragma unroll
    for (int q = 0; q < 4; q++) {
        int f = t + q * 256;
        int l = f >> 4, c4 = f & 15;
        *(float4*)&V_s[l * 64 + c4 * 4] = *(const float4*)(Vg + l * DD + c4 * 4);
    }
    const float* Pgp = g_P + (size_t)b * LL * NN;
#pragma unroll
    for (int q = 0; q < 8; q++) {
        int f = t + q * 256;
        *(float4*)&P_s[f * 4] = *(const float4*)(Pgp + f * 4);
    }
    __syncthreads();

    unsigned long long acc[8][2];
#pragma unroll
    for (int nn = 0; nn < 8; nn++) { acc[nn][0] = 0ull; acc[nn][1] = 0ull; }

#pragma unroll 4
    for (int l = 0; l < LL; l++) {
        float v0 = V_s[l * 64 + dq];
        float v1 = V_s[l * 64 + dq + 32];
        unsigned long long bv0 = pack2(v0, v0), bv1 = pack2(v1, v1);
#pragma unroll
        for (int nn = 0; nn < 8; nn++) {
            int np = ng * 8 + nn;
            unsigned long long a = *(const unsigned long long*)&P_s[l * 128 + np * 2];
            ffma2(acc[nn][0], a, bv0);
            ffma2(acc[nn][1], a, bv1);
        }
    }
    float* ob = out + 1 + (size_t)b * NN * DD + dc * 64;
#pragma unroll
    for (int nn = 0; nn < 8; nn++) {
        int n0 = (ng * 8 + nn) * 2;
        float2 v0 = unpack2(acc[nn][0]);
        float2 v1 = unpack2(acc[nn][1]);
        ob[(size_t)n0 * DD + dq]            = v0.x;
        ob[(size_t)(n0 + 1) * DD + dq]      = v0.y;
        ob[(size_t)n0 * DD + 32 + dq]       = v1.x;
        ob[(size_t)(n0 + 1) * DD + 32 + dq] = v1.y;
    }
}

// ---------------------------------------------------------------------------
extern "C" void kernel_launch(void* const* d_in, const int* in_sizes, int n_in,
                              void* d_out, int out_size)
{
    (void)in_sizes; (void)n_in; (void)out_size;
    const float* text = (const float*)d_in[0];
    const float* img  = (const float*)d_in[1];
    const int* tmask  = (const int*)d_in[2];
    const int* imask  = (const int*)d_in[3];
    float* out = (float*)d_out;

    cudaFuncSetAttribute(ground10, cudaFuncAttributeMaxDynamicSharedMemorySize, NSTG * STGB);
    cudaFuncSetAttribute(i2s_kernel, cudaFuncAttributeMaxDynamicSharedMemorySize, 49152);

    conv2<<<dim3(BB, 4), 256>>>(text, img, tmask, imask);
    ground10<<<dim3(32, BB), 256, NSTG * STGB>>>(tmask);
    loss_kernel<<<1, 64>>>(out);
    i2s_kernel<<<dim3(12, BB), 256, 49152>>>(img, out);
}